// round 16
// baseline (speedup 1.0000x reference)
#include <cuda_runtime.h>
#include <cstdint>

// ---------------------------------------------------------------------------
// Problem constants: B=4, E=400000, N_NODES=50000, N_REL=500, D=64, D_LG=256,
// K_PER_VI=20, N_MEM=131072. Scratch via device globals (no allocation).
// ---------------------------------------------------------------------------
__device__ float g_hc[131072 * 64];   // tanh(hidden_con @ Wc + bc)
__device__ float g_hu[50000 * 64];    // tanh(hidden_uncon @ Wu + bu)

// ---------------- packed f32x2 helpers (sm_103a) ----------------
__device__ __forceinline__ void unpack2(unsigned long long u, float& x, float& y) {
    asm("mov.b64 {%0,%1}, %2;" : "=f"(x), "=f"(y) : "l"(u));
}
__device__ __forceinline__ unsigned long long dup2(float x) {
    unsigned long long u;
    asm("mov.b64 %0, {%1,%1};" : "=l"(u) : "f"(x));
    return u;
}
__device__ __forceinline__ void fma2(unsigned long long& d,
                                     unsigned long long a, unsigned long long b) {
    asm("fma.rn.f32x2 %0, %1, %2, %0;" : "+l"(d) : "l"(a), "l"(b));
}

__device__ __forceinline__ float tanh_fast(float x) {
    float e = __expf(-2.0f * fabsf(x));
    float t = (1.0f - e) / (1.0f + e);
    return copysignf(t, x);
}

// ---------------------------------------------------------------------------
// Projection v8b (round-12 version, known 74us): cp.async double-buffered
// pipeline for X and W, float4 x-loads, heavy hu (K=256) blocks first.
// Thread tile 2 rows x 16 cols. Smem: X[128][36]x2 | W[32][64]x2 = 53,248 B.
// (R13 tile reshape and R15 bank padding both failed to beat this — proj is
// dual-saturated at fma~51% / L1tex~71%; layout work on it is closed.)
// ---------------------------------------------------------------------------
template <int K>
__device__ __forceinline__ void proj_tile_async(
    const float* __restrict__ X, const float* __restrict__ W,
    const float* __restrict__ bias, float* __restrict__ out,
    int rows, int bid, float* sm)
{
    constexpr int NC = K / 32;
    float* xbuf[2] = {sm, sm + 4608};
    float* wbuf[2] = {sm + 9216, sm + 11264};

    const int tid  = threadIdx.x;
    const int lane = tid & 31;
    const int warp = tid >> 5;
    const int cg   = lane >> 3;
    const int rp   = lane & 7;
    const int r0   = bid * 128;
    const int row0 = warp * 16 + rp;

    unsigned int xs[2], wsm[2];
    xs[0]  = (unsigned int)__cvta_generic_to_shared(xbuf[0]);
    xs[1]  = (unsigned int)__cvta_generic_to_shared(xbuf[1]);
    wsm[0] = (unsigned int)__cvta_generic_to_shared(wbuf[0]);
    wsm[1] = (unsigned int)__cvta_generic_to_shared(wbuf[1]);

    auto issue_chunk = [&](int c) {
        const int k0 = c * 32;
        const unsigned int xdst = xs[c & 1];
        const unsigned int wdst = wsm[c & 1];
#pragma unroll
        for (int p = 0; p < 4; p++) {
            int idx = tid + p * 256;
            int row = idx >> 3, c16 = idx & 7;
            int grow = r0 + row;
            int sz = (grow < rows) ? 16 : 0;
            if (grow >= rows) grow = rows - 1;
            const float* src = X + (size_t)grow * K + k0 + 4 * c16;
            unsigned int dst = xdst + (unsigned int)(row * 36 + 4 * c16) * 4u;
            asm volatile("cp.async.ca.shared.global [%0], [%1], 16, %2;"
                         :: "r"(dst), "l"(src), "r"(sz) : "memory");
        }
#pragma unroll
        for (int p = 0; p < 2; p++) {
            int idx = tid + p * 256;
            const float* src = W + (size_t)k0 * 64 + 4 * idx;
            unsigned int dst = wdst + (unsigned int)(4 * idx) * 4u;
            asm volatile("cp.async.ca.shared.global [%0], [%1], 16;"
                         :: "r"(dst), "l"(src) : "memory");
        }
        asm volatile("cp.async.commit_group;" ::: "memory");
    };

    unsigned long long acc[2][8];
#pragma unroll
    for (int r = 0; r < 2; r++)
#pragma unroll
        for (int j = 0; j < 8; j++) acc[r][j] = 0ull;

    issue_chunk(0);

#pragma unroll
    for (int c = 0; c < NC; c++) {
        if (c + 1 < NC) {
            issue_chunk(c + 1);
            asm volatile("cp.async.wait_group 1;" ::: "memory");
        } else {
            asm volatile("cp.async.wait_group 0;" ::: "memory");
        }
        __syncthreads();

        const float4* xb0 = reinterpret_cast<const float4*>(
                                xbuf[c & 1] + (size_t)row0 * 36);
        const float4* xb1 = reinterpret_cast<const float4*>(
                                xbuf[c & 1] + (size_t)(row0 + 8) * 36);
        const float* wb = wbuf[c & 1] + cg * 16;
#pragma unroll
        for (int k4 = 0; k4 < 8; k4++) {
            float4 xq0 = xb0[k4];
            float4 xq1 = xb1[k4];
            const float x0[4] = {xq0.x, xq0.y, xq0.z, xq0.w};
            const float x1[4] = {xq1.x, xq1.y, xq1.z, xq1.w};
#pragma unroll
            for (int t = 0; t < 4; t++) {
                unsigned long long d0 = dup2(x0[t]);
                unsigned long long d1 = dup2(x1[t]);
                const ulonglong2* wp = reinterpret_cast<const ulonglong2*>(
                    wb + (size_t)(4 * k4 + t) * 64);
                ulonglong2 wA = wp[0], wB = wp[1], wC = wp[2], wD = wp[3];
                unsigned long long wv[8] = {wA.x, wA.y, wB.x, wB.y,
                                            wC.x, wC.y, wD.x, wD.y};
#pragma unroll
                for (int j = 0; j < 8; j++) fma2(acc[0][j], d0, wv[j]);
#pragma unroll
                for (int j = 0; j < 8; j++) fma2(acc[1][j], d1, wv[j]);
            }
        }
        __syncthreads();
    }

    // ---- epilogue: bias + tanh, stage to smem [128][68], coalesced stores --
    float bv[16];
#pragma unroll
    for (int j = 0; j < 16; j++) bv[j] = __ldg(&bias[cg * 16 + j]);
#pragma unroll
    for (int r = 0; r < 2; r++) {
        int row = row0 + 8 * r;
        float* dst = &sm[(size_t)row * 68 + cg * 16];
#pragma unroll
        for (int j = 0; j < 8; j++) {
            float a, b;
            unpack2(acc[r][j], a, b);
            *reinterpret_cast<float2*>(dst + 2 * j) =
                make_float2(tanh_fast(a + bv[2 * j]), tanh_fast(b + bv[2 * j + 1]));
        }
    }
    __syncthreads();
#pragma unroll
    for (int i = 0; i < 8; i++) {
        int idx = tid + i * 256;
        int row = idx >> 4, c4 = idx & 15;
        if (r0 + row < rows)
            *reinterpret_cast<float4*>(&out[(size_t)(r0 + row) * 64 + 4 * c4]) =
                *reinterpret_cast<const float4*>(&sm[(size_t)row * 68 + 4 * c4]);
    }
}

__global__ void __launch_bounds__(256, 3) proj_both_kernel(
    const float* __restrict__ Xc, const float* __restrict__ Wc,
    const float* __restrict__ bc, int rows_c,
    const float* __restrict__ Xu, const float* __restrict__ Wu,
    const float* __restrict__ bu, int rows_u, int nb_u)
{
    extern __shared__ float sm[];
    if ((int)blockIdx.x < nb_u) {
        proj_tile_async<256>(Xu, Wu, bu, g_hu, rows_u, blockIdx.x, sm);
    } else {
        proj_tile_async<64>(Xc, Wc, bc, g_hc, rows_c, blockIdx.x - nb_u, sm);
    }
}

// ---------------------------------------------------------------------------
// Edge kernel v6 = v4 + register diet for 4 blocks/SM (40 warps):
//   __launch_bounds__(320, 4) (<=51 regs) and the 4 rel_table gathers moved
//   AFTER the weights barrier (rel_table is 128KB, L1/L2-hot from massive
//   reuse; its latency is covered at 40 warps). Peak front-batched state
//   drops 17 -> 13 float2.
// ---------------------------------------------------------------------------
__global__ void __launch_bounds__(320, 4) edge_kernel(
    const float* __restrict__ natt, const int* __restrict__ edges,
    const float* __restrict__ edges_y, const float* __restrict__ rel_table,
    const float* __restrict__ ws, const float* __restrict__ fb,
    const float* __restrict__ out_w,
    float* __restrict__ out, int n_nodes)
{
    __shared__ __align__(16) float s_w[640];   // ws[512] | fb[64] | ow[64]
    __shared__ float s_logit[2][20];

    const int tid   = threadIdx.x;
    const int wid   = tid >> 5;            // 0..9
    const int lane  = tid & 31;
    const int seg_l = wid / 5;             // 0..1
    const int wis   = wid - seg_l * 5;     // 0..4

    const long long e_base = (long long)blockIdx.x * 40 + seg_l * 20 + wis * 4;

    int4 a = make_int4(0, 0, 0, 0);
    if (lane < 8)
        a = __ldg(&reinterpret_cast<const int4*>(edges)[2 * e_base + lane]);

    const int eg    = __shfl_sync(0xFFFFFFFFu, a.x, 0);
    const int vi    = __shfl_sync(0xFFFFFFFFu, a.y, 0);
    const int vj0   = __shfl_sync(0xFFFFFFFFu, a.z, 0);
    const int rel0  = __shfl_sync(0xFFFFFFFFu, a.w, 0);
    const int e2vi0 = __shfl_sync(0xFFFFFFFFu, a.z, 1);
    const int e2vj0 = __shfl_sync(0xFFFFFFFFu, a.w, 1);
    const int vj1   = __shfl_sync(0xFFFFFFFFu, a.z, 2);
    const int rel1  = __shfl_sync(0xFFFFFFFFu, a.w, 2);
    const int e2vi1 = __shfl_sync(0xFFFFFFFFu, a.z, 3);
    const int e2vj1 = __shfl_sync(0xFFFFFFFFu, a.w, 3);
    const int vj2   = __shfl_sync(0xFFFFFFFFu, a.z, 4);
    const int rel2  = __shfl_sync(0xFFFFFFFFu, a.w, 4);
    const int e2vi2 = __shfl_sync(0xFFFFFFFFu, a.z, 5);
    const int e2vj2 = __shfl_sync(0xFFFFFFFFu, a.w, 5);
    const int vj3   = __shfl_sync(0xFFFFFFFFu, a.z, 6);
    const int rel3  = __shfl_sync(0xFFFFFFFFu, a.w, 6);
    const int e2vi3 = __shfl_sync(0xFFFFFFFFu, a.z, 7);
    const int e2vj3 = __shfl_sync(0xFFFFFFFFu, a.w, 7);
    const int vjL   = __shfl_sync(0xFFFFFFFFu, a.z, 2 * (lane & 3));

    {
        int i = tid;
        s_w[i] = (i < 512) ? __ldg(&ws[i])
                           : (i < 576 ? __ldg(&fb[i - 512]) : __ldg(&out_w[i - 576]));
        int i2 = tid + 320;
        s_w[i2] = (i2 < 512) ? __ldg(&ws[i2])
                             : (i2 < 576 ? __ldg(&fb[i2 - 512]) : __ldg(&out_w[i2 - 576]));
    }

    // front-batched gathers (13 float2: hc/hu rows, f1) + scalars
    const int d = 2 * lane;
    const float2 f0a = __ldg(reinterpret_cast<const float2*>(&g_hc[(size_t)e2vi0 * 64 + d]));
    const float2 f0b = __ldg(reinterpret_cast<const float2*>(&g_hc[(size_t)e2vi1 * 64 + d]));
    const float2 f0c = __ldg(reinterpret_cast<const float2*>(&g_hc[(size_t)e2vi2 * 64 + d]));
    const float2 f0d = __ldg(reinterpret_cast<const float2*>(&g_hc[(size_t)e2vi3 * 64 + d]));
    const float2 f3a = __ldg(reinterpret_cast<const float2*>(&g_hc[(size_t)e2vj0 * 64 + d]));
    const float2 f3b = __ldg(reinterpret_cast<const float2*>(&g_hc[(size_t)e2vj1 * 64 + d]));
    const float2 f3c = __ldg(reinterpret_cast<const float2*>(&g_hc[(size_t)e2vj2 * 64 + d]));
    const float2 f3d = __ldg(reinterpret_cast<const float2*>(&g_hc[(size_t)e2vj3 * 64 + d]));
    const float2 f4a = __ldg(reinterpret_cast<const float2*>(&g_hu[(size_t)vj0 * 64 + d]));
    const float2 f4b = __ldg(reinterpret_cast<const float2*>(&g_hu[(size_t)vj1 * 64 + d]));
    const float2 f4c = __ldg(reinterpret_cast<const float2*>(&g_hu[(size_t)vj2 * 64 + d]));
    const float2 f4d = __ldg(reinterpret_cast<const float2*>(&g_hu[(size_t)vj3 * 64 + d]));
    const float2 f1  = __ldg(reinterpret_cast<const float2*>(&g_hu[(size_t)vi * 64 + d]));
    const float att  = __ldg(&natt[(size_t)eg * n_nodes + vi]);
    const float ey   = (lane < 4) ? __ldg(&edges_y[e_base + lane]) : 0.0f;

    __syncthreads();   // weights staged

    // rel_table gathers AFTER the barrier (L1-hot; latency covered at occ 4)
    const float2 f2a = __ldg(reinterpret_cast<const float2*>(&rel_table[(size_t)rel0 * 64 + d]));
    const float2 f2b = __ldg(reinterpret_cast<const float2*>(&rel_table[(size_t)rel1 * 64 + d]));
    const float2 f2c = __ldg(reinterpret_cast<const float2*>(&rel_table[(size_t)rel2 * 64 + d]));
    const float2 f2d = __ldg(reinterpret_cast<const float2*>(&rel_table[(size_t)rel3 * 64 + d]));

    const float2 w0 = *reinterpret_cast<const float2*>(&s_w[0 * 64 + d]);
    const float2 w1 = *reinterpret_cast<const float2*>(&s_w[1 * 64 + d]);
    const float2 w2 = *reinterpret_cast<const float2*>(&s_w[2 * 64 + d]);
    const float2 w3 = *reinterpret_cast<const float2*>(&s_w[3 * 64 + d]);
    const float2 w4 = *reinterpret_cast<const float2*>(&s_w[4 * 64 + d]);
    const float2 w5 = *reinterpret_cast<const float2*>(&s_w[5 * 64 + d]);
    const float2 w6 = *reinterpret_cast<const float2*>(&s_w[6 * 64 + d]);
    const float2 w7 = *reinterpret_cast<const float2*>(&s_w[7 * 64 + d]);
    const float2 vb = *reinterpret_cast<const float2*>(&s_w[512 + d]);
    const float2 ow = *reinterpret_cast<const float2*>(&s_w[576 + d]);

    const float h4x = f1.x * w4.x, h4y = f1.y * w4.y;
    const float h5x = f1.x * w5.x, h5y = f1.y * w5.y;
    const float h6x = f1.x * w6.x, h6y = f1.y * w6.y;
    const float h7x = f1.x * w7.x, h7y = f1.y * w7.y;

#define EDGE_LOGIT(f0v, f2v, f3v, f4v, lout)                                     \
    {                                                                            \
        float a1x = f0v.x * f2v.x, a1y = f0v.y * f2v.y;                          \
        float c3x = fmaf(f0v.x, w0.x, fmaf(a1x, w1.x, fmaf(f2v.x, h5x, h4x)));   \
        float c3y = fmaf(f0v.y, w0.y, fmaf(a1y, w1.y, fmaf(f2v.y, h5y, h4y)));   \
        float c4x = fmaf(f0v.x, w2.x, fmaf(a1x, w3.x, fmaf(f2v.x, h7x, h6x)));   \
        float c4y = fmaf(f0v.y, w2.y, fmaf(a1y, w3.y, fmaf(f2v.y, h7y, h6y)));   \
        float oxv = fmaf(f3v.x, c3x, fmaf(f4v.x, c4x, vb.x));                    \
        float oyv = fmaf(f3v.y, c3y, fmaf(f4v.y, c4y, vb.y));                    \
        lout = fmaf(fmaxf(oxv, 0.0f), ow.x, fmaxf(oyv, 0.0f) * ow.y);            \
    }

    float l0, l1, l2, l3;
    EDGE_LOGIT(f0a, f2a, f3a, f4a, l0)
    EDGE_LOGIT(f0b, f2b, f3b, f4b, l1)
    EDGE_LOGIT(f0c, f2c, f3c, f4c, l2)
    EDGE_LOGIT(f0d, f2d, f3d, f4d, l3)
#undef EDGE_LOGIT

#pragma unroll
    for (int s = 16; s > 0; s >>= 1) {
        l0 += __shfl_xor_sync(0xFFFFFFFFu, l0, s);
        l1 += __shfl_xor_sync(0xFFFFFFFFu, l1, s);
        l2 += __shfl_xor_sync(0xFFFFFFFFu, l2, s);
        l3 += __shfl_xor_sync(0xFFFFFFFFu, l3, s);
    }
    if (lane == 0) {
        s_logit[seg_l][wis * 4 + 0] = l0;
        s_logit[seg_l][wis * 4 + 1] = l1;
        s_logit[seg_l][wis * 4 + 2] = l2;
        s_logit[seg_l][wis * 4 + 3] = l3;
    }
    __syncthreads();

    float l = (lane < 20) ? s_logit[seg_l][lane] : -1e30f;
    float m = l;
#pragma unroll
    for (int s = 16; s > 0; s >>= 1) m = fmaxf(m, __shfl_xor_sync(0xFFFFFFFFu, m, s));
    float ev = (lane < 20) ? __expf(l - m) : 0.0f;
#pragma unroll
    for (int s = 16; s > 0; s >>= 1) ev += __shfl_xor_sync(0xFFFFFFFFu, ev, s);

    if (lane < 4) {
        float lg = s_logit[seg_l][wis * 4 + lane];
        float trans = __expf(lg - m) / ev;
        atomicAdd(&out[(size_t)eg * n_nodes + vjL], trans * att * ey);
    }
}

// ---------------------------------------------------------------------------
extern "C" void kernel_launch(void* const* d_in, const int* in_sizes, int n_in,
                              void* d_out, int out_size)
{
    const float* natt    = (const float*)d_in[0];
    const int*   edges   = (const int*)d_in[1];
    const float* edges_y = (const float*)d_in[2];
    const float* hu_in   = (const float*)d_in[3];   // [1, n_nodes, 256]
    const float* hc_in   = (const float*)d_in[4];   // [n_mem, 64]
    const float* Wc      = (const float*)d_in[5];
    const float* bc      = (const float*)d_in[6];
    const float* Wu      = (const float*)d_in[7];
    const float* bu      = (const float*)d_in[8];
    const float* rel_t   = (const float*)d_in[9];
    const float* ws      = (const float*)d_in[10];
    const float* fb      = (const float*)d_in[11];
    const float* ow      = (const float*)d_in[12];

    const int E       = in_sizes[2];
    const int n_nodes = in_sizes[3] / 256;
    const int n_mem   = in_sizes[4] / 64;
    const int n_seg   = E / 20;

    const int nb_c = (n_mem + 127) / 128;      // 1024
    const int nb_u = (n_nodes + 127) / 128;    // 391

    const int dyn_smem = 13312 * 4;            // 53,248 bytes
    cudaFuncSetAttribute(proj_both_kernel,
                         cudaFuncAttributeMaxDynamicSharedMemorySize, dyn_smem);
    cudaFuncSetAttribute(proj_both_kernel,
                         cudaFuncAttributePreferredSharedMemoryCarveout, 100);

    cudaMemsetAsync(d_out, 0, (size_t)out_size * sizeof(float));     // launch 1

    proj_both_kernel<<<nb_c + nb_u, 256, dyn_smem>>>(                // launch 2
        hc_in, Wc, bc, n_mem, hu_in, Wu, bu, n_nodes, nb_u);

    edge_kernel<<<n_seg / 2, 320>>>(natt, edges, edges_y, rel_t,     // launch 3
                                    ws, fb, ow, (float*)d_out, n_nodes);
}

// round 17
// speedup vs baseline: 1.0371x; 1.0371x over previous
#include <cuda_runtime.h>
#include <cstdint>

// ---------------------------------------------------------------------------
// Problem constants: B=4, E=400000, N_NODES=50000, N_REL=500, D=64, D_LG=256,
// K_PER_VI=20, N_MEM=131072. Scratch via device globals (no allocation).
//
// Champion config (round 12, 137.1us):
//   memset | proj_both (cp.async pipelined, heavy-first) | dummy | edge v4
// R13 (4x8 tile), R14 (hu compaction), R15 (W bank padding), R16 (edge
// occupancy) all regressed or were neutral — this restores the verified best.
// ---------------------------------------------------------------------------
__device__ float g_hc[131072 * 64];   // tanh(hidden_con @ Wc + bc)
__device__ float g_hu[50000 * 64];    // tanh(hidden_uncon @ Wu + bu)

// ---------------- packed f32x2 helpers (sm_103a) ----------------
__device__ __forceinline__ void unpack2(unsigned long long u, float& x, float& y) {
    asm("mov.b64 {%0,%1}, %2;" : "=f"(x), "=f"(y) : "l"(u));
}
__device__ __forceinline__ unsigned long long dup2(float x) {
    unsigned long long u;
    asm("mov.b64 %0, {%1,%1};" : "=l"(u) : "f"(x));
    return u;
}
__device__ __forceinline__ void fma2(unsigned long long& d,
                                     unsigned long long a, unsigned long long b) {
    asm("fma.rn.f32x2 %0, %1, %2, %0;" : "+l"(d) : "l"(a), "l"(b));
}

__device__ __forceinline__ float tanh_fast(float x) {
    float e = __expf(-2.0f * fabsf(x));
    float t = (1.0f - e) / (1.0f + e);
    return copysignf(t, x);
}

// ---------------------------------------------------------------------------
// Projection v8b (round-12, 74.1us measured): cp.async double-buffered
// pipeline for X and W, float4 x-loads, heavy hu (K=256) blocks first.
// Thread tile 2 rows x 16 cols. Smem: X[128][36]x2 | W[32][64]x2 = 53,248 B.
// 3 blocks/SM at 80 regs. fma 51.7% / L1tex 71.4% (dual-saturated; all
// layout reshapes falsified as improvements in R13/R15).
// ---------------------------------------------------------------------------
template <int K>
__device__ __forceinline__ void proj_tile_async(
    const float* __restrict__ X, const float* __restrict__ W,
    const float* __restrict__ bias, float* __restrict__ out,
    int rows, int bid, float* sm)
{
    constexpr int NC = K / 32;
    float* xbuf[2] = {sm, sm + 4608};
    float* wbuf[2] = {sm + 9216, sm + 11264};

    const int tid  = threadIdx.x;
    const int lane = tid & 31;
    const int warp = tid >> 5;
    const int cg   = lane >> 3;
    const int rp   = lane & 7;
    const int r0   = bid * 128;
    const int row0 = warp * 16 + rp;

    unsigned int xs[2], wsm[2];
    xs[0]  = (unsigned int)__cvta_generic_to_shared(xbuf[0]);
    xs[1]  = (unsigned int)__cvta_generic_to_shared(xbuf[1]);
    wsm[0] = (unsigned int)__cvta_generic_to_shared(wbuf[0]);
    wsm[1] = (unsigned int)__cvta_generic_to_shared(wbuf[1]);

    auto issue_chunk = [&](int c) {
        const int k0 = c * 32;
        const unsigned int xdst = xs[c & 1];
        const unsigned int wdst = wsm[c & 1];
#pragma unroll
        for (int p = 0; p < 4; p++) {
            int idx = tid + p * 256;
            int row = idx >> 3, c16 = idx & 7;
            int grow = r0 + row;
            int sz = (grow < rows) ? 16 : 0;
            if (grow >= rows) grow = rows - 1;
            const float* src = X + (size_t)grow * K + k0 + 4 * c16;
            unsigned int dst = xdst + (unsigned int)(row * 36 + 4 * c16) * 4u;
            asm volatile("cp.async.ca.shared.global [%0], [%1], 16, %2;"
                         :: "r"(dst), "l"(src), "r"(sz) : "memory");
        }
#pragma unroll
        for (int p = 0; p < 2; p++) {
            int idx = tid + p * 256;
            const float* src = W + (size_t)k0 * 64 + 4 * idx;
            unsigned int dst = wdst + (unsigned int)(4 * idx) * 4u;
            asm volatile("cp.async.ca.shared.global [%0], [%1], 16;"
                         :: "r"(dst), "l"(src) : "memory");
        }
        asm volatile("cp.async.commit_group;" ::: "memory");
    };

    unsigned long long acc[2][8];
#pragma unroll
    for (int r = 0; r < 2; r++)
#pragma unroll
        for (int j = 0; j < 8; j++) acc[r][j] = 0ull;

    issue_chunk(0);

#pragma unroll
    for (int c = 0; c < NC; c++) {
        if (c + 1 < NC) {
            issue_chunk(c + 1);
            asm volatile("cp.async.wait_group 1;" ::: "memory");
        } else {
            asm volatile("cp.async.wait_group 0;" ::: "memory");
        }
        __syncthreads();

        const float4* xb0 = reinterpret_cast<const float4*>(
                                xbuf[c & 1] + (size_t)row0 * 36);
        const float4* xb1 = reinterpret_cast<const float4*>(
                                xbuf[c & 1] + (size_t)(row0 + 8) * 36);
        const float* wb = wbuf[c & 1] + cg * 16;
#pragma unroll
        for (int k4 = 0; k4 < 8; k4++) {
            float4 xq0 = xb0[k4];
            float4 xq1 = xb1[k4];
            const float x0[4] = {xq0.x, xq0.y, xq0.z, xq0.w};
            const float x1[4] = {xq1.x, xq1.y, xq1.z, xq1.w};
#pragma unroll
            for (int t = 0; t < 4; t++) {
                unsigned long long d0 = dup2(x0[t]);
                unsigned long long d1 = dup2(x1[t]);
                const ulonglong2* wp = reinterpret_cast<const ulonglong2*>(
                    wb + (size_t)(4 * k4 + t) * 64);
                ulonglong2 wA = wp[0], wB = wp[1], wC = wp[2], wD = wp[3];
                unsigned long long wv[8] = {wA.x, wA.y, wB.x, wB.y,
                                            wC.x, wC.y, wD.x, wD.y};
#pragma unroll
                for (int j = 0; j < 8; j++) fma2(acc[0][j], d0, wv[j]);
#pragma unroll
                for (int j = 0; j < 8; j++) fma2(acc[1][j], d1, wv[j]);
            }
        }
        __syncthreads();
    }

    // ---- epilogue: bias + tanh, stage to smem [128][68], coalesced stores --
    float bv[16];
#pragma unroll
    for (int j = 0; j < 16; j++) bv[j] = __ldg(&bias[cg * 16 + j]);
#pragma unroll
    for (int r = 0; r < 2; r++) {
        int row = row0 + 8 * r;
        float* dst = &sm[(size_t)row * 68 + cg * 16];
#pragma unroll
        for (int j = 0; j < 8; j++) {
            float a, b;
            unpack2(acc[r][j], a, b);
            *reinterpret_cast<float2*>(dst + 2 * j) =
                make_float2(tanh_fast(a + bv[2 * j]), tanh_fast(b + bv[2 * j + 1]));
        }
    }
    __syncthreads();
#pragma unroll
    for (int i = 0; i < 8; i++) {
        int idx = tid + i * 256;
        int row = idx >> 4, c4 = idx & 15;
        if (r0 + row < rows)
            *reinterpret_cast<float4*>(&out[(size_t)(r0 + row) * 64 + 4 * c4]) =
                *reinterpret_cast<const float4*>(&sm[(size_t)row * 68 + 4 * c4]);
    }
}

__global__ void __launch_bounds__(256, 3) proj_both_kernel(
    const float* __restrict__ Xc, const float* __restrict__ Wc,
    const float* __restrict__ bc, int rows_c,
    const float* __restrict__ Xu, const float* __restrict__ Wu,
    const float* __restrict__ bu, int rows_u, int nb_u)
{
    extern __shared__ float sm[];
    // heavy hu (K=256) blocks first: light hc blocks form the tail
    if ((int)blockIdx.x < nb_u) {
        proj_tile_async<256>(Xu, Wu, bu, g_hu, rows_u, blockIdx.x, sm);
    } else {
        proj_tile_async<64>(Xc, Wc, bc, g_hc, rows_c, blockIdx.x - nb_u, sm);
    }
}

// Tiny no-op kernel: keeps ncu's "-s 5 -c 1" capture landing on proj.
__global__ void capture_align_kernel() {}

// ---------------------------------------------------------------------------
// Edge kernel v4 (round-6/12 version, 64.0us measured): 2 segments per
// 320-thread block, 5 warps/segment, 4 edges/warp. Weights staged in smem
// once per block; ALL gathers (incl. rel_table) front-batched before the
// single barrier — R11 (dual-row LDG.128) and R16 (deferred rel gathers +
// occupancy 4) both regressed; this MLP-17 shape is the validated optimum.
// out_b dropped (softmax-invariant constant).
// ---------------------------------------------------------------------------
__global__ void __launch_bounds__(320, 3) edge_kernel(
    const float* __restrict__ natt, const int* __restrict__ edges,
    const float* __restrict__ edges_y, const float* __restrict__ rel_table,
    const float* __restrict__ ws, const float* __restrict__ fb,
    const float* __restrict__ out_w,
    float* __restrict__ out, int n_nodes)
{
    __shared__ __align__(16) float s_w[640];   // ws[512] | fb[64] | ow[64]
    __shared__ float s_logit[2][20];

    const int tid   = threadIdx.x;
    const int wid   = tid >> 5;            // 0..9
    const int lane  = tid & 31;
    const int seg_l = wid / 5;             // 0..1
    const int wis   = wid - seg_l * 5;     // 0..4

    const long long e_base = (long long)blockIdx.x * 40 + seg_l * 20 + wis * 4;

    int4 a = make_int4(0, 0, 0, 0);
    if (lane < 8)
        a = __ldg(&reinterpret_cast<const int4*>(edges)[2 * e_base + lane]);

    const int eg    = __shfl_sync(0xFFFFFFFFu, a.x, 0);
    const int vi    = __shfl_sync(0xFFFFFFFFu, a.y, 0);
    const int vj0   = __shfl_sync(0xFFFFFFFFu, a.z, 0);
    const int rel0  = __shfl_sync(0xFFFFFFFFu, a.w, 0);
    const int e2vi0 = __shfl_sync(0xFFFFFFFFu, a.z, 1);
    const int e2vj0 = __shfl_sync(0xFFFFFFFFu, a.w, 1);
    const int vj1   = __shfl_sync(0xFFFFFFFFu, a.z, 2);
    const int rel1  = __shfl_sync(0xFFFFFFFFu, a.w, 2);
    const int e2vi1 = __shfl_sync(0xFFFFFFFFu, a.z, 3);
    const int e2vj1 = __shfl_sync(0xFFFFFFFFu, a.w, 3);
    const int vj2   = __shfl_sync(0xFFFFFFFFu, a.z, 4);
    const int rel2  = __shfl_sync(0xFFFFFFFFu, a.w, 4);
    const int e2vi2 = __shfl_sync(0xFFFFFFFFu, a.z, 5);
    const int e2vj2 = __shfl_sync(0xFFFFFFFFu, a.w, 5);
    const int vj3   = __shfl_sync(0xFFFFFFFFu, a.z, 6);
    const int rel3  = __shfl_sync(0xFFFFFFFFu, a.w, 6);
    const int e2vi3 = __shfl_sync(0xFFFFFFFFu, a.z, 7);
    const int e2vj3 = __shfl_sync(0xFFFFFFFFu, a.w, 7);
    const int vjL   = __shfl_sync(0xFFFFFFFFu, a.z, 2 * (lane & 3));

    {
        int i = tid;
        s_w[i] = (i < 512) ? __ldg(&ws[i])
                           : (i < 576 ? __ldg(&fb[i - 512]) : __ldg(&out_w[i - 576]));
        int i2 = tid + 320;
        s_w[i2] = (i2 < 512) ? __ldg(&ws[i2])
                             : (i2 < 576 ? __ldg(&fb[i2 - 512]) : __ldg(&out_w[i2 - 576]));
    }

    const int d = 2 * lane;
    const float2 f0a = __ldg(reinterpret_cast<const float2*>(&g_hc[(size_t)e2vi0 * 64 + d]));
    const float2 f0b = __ldg(reinterpret_cast<const float2*>(&g_hc[(size_t)e2vi1 * 64 + d]));
    const float2 f0c = __ldg(reinterpret_cast<const float2*>(&g_hc[(size_t)e2vi2 * 64 + d]));
    const float2 f0d = __ldg(reinterpret_cast<const float2*>(&g_hc[(size_t)e2vi3 * 64 + d]));
    const float2 f3a = __ldg(reinterpret_cast<const float2*>(&g_hc[(size_t)e2vj0 * 64 + d]));
    const float2 f3b = __ldg(reinterpret_cast<const float2*>(&g_hc[(size_t)e2vj1 * 64 + d]));
    const float2 f3c = __ldg(reinterpret_cast<const float2*>(&g_hc[(size_t)e2vj2 * 64 + d]));
    const float2 f3d = __ldg(reinterpret_cast<const float2*>(&g_hc[(size_t)e2vj3 * 64 + d]));
    const float2 f4a = __ldg(reinterpret_cast<const float2*>(&g_hu[(size_t)vj0 * 64 + d]));
    const float2 f4b = __ldg(reinterpret_cast<const float2*>(&g_hu[(size_t)vj1 * 64 + d]));
    const float2 f4c = __ldg(reinterpret_cast<const float2*>(&g_hu[(size_t)vj2 * 64 + d]));
    const float2 f4d = __ldg(reinterpret_cast<const float2*>(&g_hu[(size_t)vj3 * 64 + d]));
    const float2 f2a = __ldg(reinterpret_cast<const float2*>(&rel_table[(size_t)rel0 * 64 + d]));
    const float2 f2b = __ldg(reinterpret_cast<const float2*>(&rel_table[(size_t)rel1 * 64 + d]));
    const float2 f2c = __ldg(reinterpret_cast<const float2*>(&rel_table[(size_t)rel2 * 64 + d]));
    const float2 f2d = __ldg(reinterpret_cast<const float2*>(&rel_table[(size_t)rel3 * 64 + d]));
    const float2 f1  = __ldg(reinterpret_cast<const float2*>(&g_hu[(size_t)vi * 64 + d]));
    const float att  = __ldg(&natt[(size_t)eg * n_nodes + vi]);
    const float ey   = (lane < 4) ? __ldg(&edges_y[e_base + lane]) : 0.0f;

    __syncthreads();

    const float2 w0 = *reinterpret_cast<const float2*>(&s_w[0 * 64 + d]);
    const float2 w1 = *reinterpret_cast<const float2*>(&s_w[1 * 64 + d]);
    const float2 w2 = *reinterpret_cast<const float2*>(&s_w[2 * 64 + d]);
    const float2 w3 = *reinterpret_cast<const float2*>(&s_w[3 * 64 + d]);
    const float2 w4 = *reinterpret_cast<const float2*>(&s_w[4 * 64 + d]);
    const float2 w5 = *reinterpret_cast<const float2*>(&s_w[5 * 64 + d]);
    const float2 w6 = *reinterpret_cast<const float2*>(&s_w[6 * 64 + d]);
    const float2 w7 = *reinterpret_cast<const float2*>(&s_w[7 * 64 + d]);
    const float2 vb = *reinterpret_cast<const float2*>(&s_w[512 + d]);
    const float2 ow = *reinterpret_cast<const float2*>(&s_w[576 + d]);

    const float h4x = f1.x * w4.x, h4y = f1.y * w4.y;
    const float h5x = f1.x * w5.x, h5y = f1.y * w5.y;
    const float h6x = f1.x * w6.x, h6y = f1.y * w6.y;
    const float h7x = f1.x * w7.x, h7y = f1.y * w7.y;

#define EDGE_LOGIT(f0v, f2v, f3v, f4v, lout)                                     \
    {                                                                            \
        float a1x = f0v.x * f2v.x, a1y = f0v.y * f2v.y;                          \
        float c3x = fmaf(f0v.x, w0.x, fmaf(a1x, w1.x, fmaf(f2v.x, h5x, h4x)));   \
        float c3y = fmaf(f0v.y, w0.y, fmaf(a1y, w1.y, fmaf(f2v.y, h5y, h4y)));   \
        float c4x = fmaf(f0v.x, w2.x, fmaf(a1x, w3.x, fmaf(f2v.x, h7x, h6x)));   \
        float c4y = fmaf(f0v.y, w2.y, fmaf(a1y, w3.y, fmaf(f2v.y, h7y, h6y)));   \
        float oxv = fmaf(f3v.x, c3x, fmaf(f4v.x, c4x, vb.x));                    \
        float oyv = fmaf(f3v.y, c3y, fmaf(f4v.y, c4y, vb.y));                    \
        lout = fmaf(fmaxf(oxv, 0.0f), ow.x, fmaxf(oyv, 0.0f) * ow.y);            \
    }

    float l0, l1, l2, l3;
    EDGE_LOGIT(f0a, f2a, f3a, f4a, l0)
    EDGE_LOGIT(f0b, f2b, f3b, f4b, l1)
    EDGE_LOGIT(f0c, f2c, f3c, f4c, l2)
    EDGE_LOGIT(f0d, f2d, f3d, f4d, l3)
#undef EDGE_LOGIT

#pragma unroll
    for (int s = 16; s > 0; s >>= 1) {
        l0 += __shfl_xor_sync(0xFFFFFFFFu, l0, s);
        l1 += __shfl_xor_sync(0xFFFFFFFFu, l1, s);
        l2 += __shfl_xor_sync(0xFFFFFFFFu, l2, s);
        l3 += __shfl_xor_sync(0xFFFFFFFFu, l3, s);
    }
    if (lane == 0) {
        s_logit[seg_l][wis * 4 + 0] = l0;
        s_logit[seg_l][wis * 4 + 1] = l1;
        s_logit[seg_l][wis * 4 + 2] = l2;
        s_logit[seg_l][wis * 4 + 3] = l3;
    }
    __syncthreads();

    float l = (lane < 20) ? s_logit[seg_l][lane] : -1e30f;
    float m = l;
#pragma unroll
    for (int s = 16; s > 0; s >>= 1) m = fmaxf(m, __shfl_xor_sync(0xFFFFFFFFu, m, s));
    float ev = (lane < 20) ? __expf(l - m) : 0.0f;
#pragma unroll
    for (int s = 16; s > 0; s >>= 1) ev += __shfl_xor_sync(0xFFFFFFFFu, ev, s);

    if (lane < 4) {
        float lg = s_logit[seg_l][wis * 4 + lane];
        float trans = __expf(lg - m) / ev;
        atomicAdd(&out[(size_t)eg * n_nodes + vjL], trans * att * ey);
    }
}

// ---------------------------------------------------------------------------
extern "C" void kernel_launch(void* const* d_in, const int* in_sizes, int n_in,
                              void* d_out, int out_size)
{
    const float* natt    = (const float*)d_in[0];
    const int*   edges   = (const int*)d_in[1];
    const float* edges_y = (const float*)d_in[2];
    const float* hu_in   = (const float*)d_in[3];   // [1, n_nodes, 256]
    const float* hc_in   = (const float*)d_in[4];   // [n_mem, 64]
    const float* Wc      = (const float*)d_in[5];
    const float* bc      = (const float*)d_in[6];
    const float* Wu      = (const float*)d_in[7];
    const float* bu      = (const float*)d_in[8];
    const float* rel_t   = (const float*)d_in[9];
    const float* ws      = (const float*)d_in[10];
    const float* fb      = (const float*)d_in[11];
    const float* ow      = (const float*)d_in[12];

    const int E       = in_sizes[2];
    const int n_nodes = in_sizes[3] / 256;
    const int n_mem   = in_sizes[4] / 64;
    const int n_seg   = E / 20;

    const int nb_c = (n_mem + 127) / 128;      // 1024
    const int nb_u = (n_nodes + 127) / 128;    // 391

    const int dyn_smem = 13312 * 4;            // 53,248 bytes
    cudaFuncSetAttribute(proj_both_kernel,
                         cudaFuncAttributeMaxDynamicSharedMemorySize, dyn_smem);
    cudaFuncSetAttribute(proj_both_kernel,
                         cudaFuncAttributePreferredSharedMemoryCarveout, 100);

    cudaMemsetAsync(d_out, 0, (size_t)out_size * sizeof(float));     // launch 1

    proj_both_kernel<<<nb_c + nb_u, 256, dyn_smem>>>(                // launch 2
        hc_in, Wc, bc, n_mem, hu_in, Wu, bu, n_nodes, nb_u);

    capture_align_kernel<<<1, 32>>>();                               // launch 3

    edge_kernel<<<n_seg / 2, 320>>>(natt, edges, edges_y, rel_t,     // launch 4
                                    ws, fb, ow, (float*)d_out, n_nodes);
}